// round 1
// baseline (speedup 1.0000x reference)
#include <cuda_runtime.h>

// Problem constants
#define PB   32            // batch
#define PT   8192          // series length
#define PC   3             // channels
#define PNS  256           // num shapelets
#define PLS  32            // shapelet length
#define PW   (PT - PLS + 1)  // 8161 windows

// Tiling
#define NCHUNK  19
#define WCHUNK  432              // 19*432 = 8208 >= 8161, multiple of 16
#define SPB     64               // shapelets per block
#define NSB     (PNS / SPB)      // 4
#define NGROUP  2                // window groups per block
#define NW      8                // windows per thread per pass
#define THREADS (SPB * NGROUP)   // 128
#define STRIP   (WCHUNK + PLS - 1)  // 463

// Device scratch (no allocations allowed)
__device__ float4 g_X[PB * PT];                            // packed (x0,x1,x2,|x|^2)
__device__ float4 g_Kp[PLS * PNS];                         // [l][s]: (-2k0,-2k1,-2k2, 1)
__device__ float  g_part[PB * NCHUNK * NGROUP * PNS];      // partial mins

typedef unsigned long long u64;

__device__ __forceinline__ u64 pk2(float lo, float hi) {
    u64 r; asm("mov.b64 %0, {%1, %2};" : "=l"(r) : "f"(lo), "f"(hi)); return r;
}
__device__ __forceinline__ void upk2(float& lo, float& hi, u64 v) {
    asm("mov.b64 {%0, %1}, %2;" : "=f"(lo), "=f"(hi) : "l"(v));
}
__device__ __forceinline__ void fma2(u64& d, u64 a, u64 b) {
    asm("fma.rn.f32x2 %0, %1, %2, %0;" : "+l"(d) : "l"(a), "l"(b));
}

// ---------------------------------------------------------------------------
// Pack data: X[b,t] = (x0, x1, x2, x0^2+x1^2+x2^2)
__global__ void pack_x_kernel(const float* __restrict__ data) {
    int i = blockIdx.x * blockDim.x + threadIdx.x;
    if (i >= PB * PT) return;
    float x0 = data[i * 3 + 0];
    float x1 = data[i * 3 + 1];
    float x2 = data[i * 3 + 2];
    g_X[i] = make_float4(x0, x1, x2, x0 * x0 + x1 * x1 + x2 * x2);
}

// Pack shapelets: Kp[l][s] = (-2k0, -2k1, -2k2, 1)
__global__ void pack_k_kernel(const float* __restrict__ ker) {
    int i = blockIdx.x * blockDim.x + threadIdx.x;  // over NS*LS
    if (i >= PNS * PLS) return;
    int s = i / PLS, l = i % PLS;
    float k0 = ker[i * 3 + 0];
    float k1 = ker[i * 3 + 1];
    float k2 = ker[i * 3 + 2];
    g_Kp[l * PNS + s] = make_float4(-2.f * k0, -2.f * k1, -2.f * k2, 1.0f);
}

// ---------------------------------------------------------------------------
// Main: dist_partial[b,s,w] = sum_l dot4(X[b,w+l], Kp[s,l]); min over chunk windows
__global__ __launch_bounds__(THREADS, 4) void shapelet_main_kernel() {
    __shared__ float4 Ksh[PLS * SPB];   // [l][sl]
    __shared__ float4 Xsh[STRIP];

    int chunk = blockIdx.x;             // 0..NCHUNK-1
    int sblk  = blockIdx.y;             // 0..NSB-1
    int b     = blockIdx.z;
    int tid   = threadIdx.x;
    int sl    = tid % SPB;              // local shapelet
    int g     = tid / SPB;              // window group (warp-uniform: SPB=64)
    int sBase = sblk * SPB;
    int w0    = chunk * WCHUNK;
    int wendL = PW - w0; if (wendL > WCHUNK) wendL = WCHUNK;   // >= 8 always

    // Load K' tile (coalesced, conflict-free [l][sl] layout)
    for (int i = tid; i < PLS * SPB; i += THREADS) {
        int l = i / SPB, s = i % SPB;
        Ksh[i] = g_Kp[l * PNS + sBase + s];
    }
    // Load data strip (clamped at T-1; clamped entries never affect valid windows)
    const float4* Xg = g_X + b * PT;
    for (int i = tid; i < STRIP; i += THREADS) {
        int t = w0 + i; if (t > PT - 1) t = PT - 1;
        Xsh[i] = Xg[t];
    }
    __syncthreads();

    float rmin = 3.4e38f;
    for (int pb = 0; pb < wendL; pb += NGROUP * NW) {
        int gw = pb + g * NW;
        if (gw > wendL - NW) gw = wendL - NW;   // clamp: duplicates are fine for min

        u64 acc[NW];
        #pragma unroll
        for (int i = 0; i < NW; i++) acc[i] = 0ull;   // (0.f, 0.f)

        const float4* kp = Ksh + sl;
        #pragma unroll
        for (int l = 0; l < PLS; l++) {
            float4 kv = kp[l * SPB];
            u64 k01 = pk2(kv.x, kv.y);
            u64 k23 = pk2(kv.z, kv.w);
            #pragma unroll
            for (int i = 0; i < NW; i++) {
                float4 xv = Xsh[gw + l + i];           // broadcast within warp
                fma2(acc[i], pk2(xv.x, xv.y), k01);
                fma2(acc[i], pk2(xv.z, xv.w), k23);
            }
        }
        #pragma unroll
        for (int i = 0; i < NW; i++) {
            float lo, hi; upk2(lo, hi, acc[i]);
            rmin = fminf(rmin, lo + hi);
        }
    }
    g_part[((b * NCHUNK + chunk) * NGROUP + g) * PNS + sBase + sl] = rmin;
}

// ---------------------------------------------------------------------------
// Reduce: out[b,s] = (min over chunks/groups + k2[s]) / LS
__global__ void reduce_out_kernel(const float* __restrict__ ker,
                                  float* __restrict__ out) {
    int s = threadIdx.x;   // 0..255
    int b = blockIdx.x;    // 0..31
    float k2 = 0.f;
    #pragma unroll 4
    for (int j = 0; j < PLS * PC; j++) {
        float v = ker[s * PLS * PC + j];
        k2 += v * v;
    }
    float m = 3.4e38f;
    const float* p = g_part + b * NCHUNK * NGROUP * PNS + s;
    #pragma unroll 4
    for (int cg = 0; cg < NCHUNK * NGROUP; cg++)
        m = fminf(m, p[cg * PNS]);
    out[b * PNS + s] = (m + k2) * (1.0f / (float)PLS);
}

// ---------------------------------------------------------------------------
extern "C" void kernel_launch(void* const* d_in, const int* in_sizes, int n_in,
                              void* d_out, int out_size) {
    const float* data = (const float*)d_in[0];   // [32, 8192, 3]
    const float* ker  = (const float*)d_in[1];   // [256, 32, 3]
    float* out = (float*)d_out;                  // [32, 256]

    pack_x_kernel<<<(PB * PT + 255) / 256, 256>>>(data);
    pack_k_kernel<<<(PNS * PLS + 255) / 256, 256>>>(ker);

    dim3 grid(NCHUNK, NSB, PB);
    shapelet_main_kernel<<<grid, THREADS>>>();

    reduce_out_kernel<<<PB, PNS>>>(ker, out);
}

// round 2
// speedup vs baseline: 1.0010x; 1.0010x over previous
#include <cuda_runtime.h>

// Problem constants
#define PB   32
#define PT   8192
#define PC   3
#define PNS  256
#define PLS  32
#define PW   (PT - PLS + 1)   // 8161

// Tiling
#define NCHUNK  19
#define WCHUNK  432               // 19*432 = 8208 >= 8161
#define SPB     64                // shapelets per block
#define NSB     (PNS / SPB)       // 4
#define NGROUP  2
#define NW      8
#define THREADS (SPB * NGROUP)    // 128
#define STRIP   (WCHUNK + PLS - 1)  // 463

typedef unsigned long long u64;
typedef unsigned int u32;

// Device scratch (allocations forbidden)
__device__ ulonglong2 g_X[PB * PT];     // packed (x0,x1 | x2,|x|^2) as two b64
__device__ ulonglong2 g_Kp[PLS * PNS];  // [l][s]: (-2k0,-2k1 | -2k2, 1)
__device__ u32        g_amin[PB * PNS]; // encoded-uint running min

__device__ __forceinline__ void fma2(u64& d, u64 a, u64 b) {
    asm("fma.rn.f32x2 %0, %1, %2, %0;" : "+l"(d) : "l"(a), "l"(b));
}
__device__ __forceinline__ void upk2(float& lo, float& hi, u64 v) {
    asm("mov.b64 {%0, %1}, %2;" : "=f"(lo), "=f"(hi) : "l"(v));
}
// order-preserving float<->uint encoding (for atomicMin on float values)
__device__ __forceinline__ u32 fenc(float f) {
    u32 u = __float_as_uint(f);
    return (u & 0x80000000u) ? ~u : (u | 0x80000000u);
}
__device__ __forceinline__ float fdec(u32 u) {
    u32 b = (u & 0x80000000u) ? (u & 0x7FFFFFFFu) : ~u;
    return __uint_as_float(b);
}

// ---------------------------------------------------------------------------
__global__ void pack_x_kernel(const float* __restrict__ data) {
    int i = blockIdx.x * blockDim.x + threadIdx.x;
    if (i >= PB * PT) return;
    float x0 = data[i * 3 + 0];
    float x1 = data[i * 3 + 1];
    float x2 = data[i * 3 + 2];
    float4 v = make_float4(x0, x1, x2, x0 * x0 + x1 * x1 + x2 * x2);
    reinterpret_cast<float4*>(g_X)[i] = v;
}

__global__ void pack_k_kernel(const float* __restrict__ ker) {
    int i = blockIdx.x * blockDim.x + threadIdx.x;  // over NS*LS
    if (i >= PNS * PLS) return;
    int s = i / PLS, l = i % PLS;
    float k0 = ker[i * 3 + 0];
    float k1 = ker[i * 3 + 1];
    float k2 = ker[i * 3 + 2];
    reinterpret_cast<float4*>(g_Kp)[l * PNS + s] =
        make_float4(-2.f * k0, -2.f * k1, -2.f * k2, 1.0f);
}

__global__ void init_amin_kernel() {
    int i = blockIdx.x * blockDim.x + threadIdx.x;
    if (i < PB * PNS) g_amin[i] = 0xFFFFFFFFu;
}

// ---------------------------------------------------------------------------
// Main: rmin[b,s] over chunk windows of sum_l dot4(X[w+l], Kp[s,l]); atomicMin out.
__global__ __launch_bounds__(THREADS, 4) void shapelet_main_kernel() {
    __shared__ ulonglong2 Ksh[PLS * SPB];   // [l][sl]
    __shared__ ulonglong2 Xsh[STRIP];

    int chunk = blockIdx.x;
    int sblk  = blockIdx.y;
    int b     = blockIdx.z;
    int tid   = threadIdx.x;
    int sl    = tid % SPB;
    int g     = tid / SPB;                   // warp-uniform (SPB=64)
    int sBase = sblk * SPB;
    int w0    = chunk * WCHUNK;
    int wendL = PW - w0; if (wendL > WCHUNK) wendL = WCHUNK;

    for (int i = tid; i < PLS * SPB; i += THREADS) {
        int l = i / SPB, s = i % SPB;
        Ksh[i] = g_Kp[l * PNS + sBase + s];
    }
    const ulonglong2* Xg = g_X + b * PT;
    for (int i = tid; i < STRIP; i += THREADS) {
        int t = w0 + i; if (t > PT - 1) t = PT - 1;   // clamp; never wins the min
        Xsh[i] = Xg[t];
    }
    __syncthreads();

    float rmin = 3.4e38f;
    for (int pb = 0; pb < wendL; pb += NGROUP * NW) {
        int gw = pb + g * NW;
        if (gw > wendL - NW) gw = wendL - NW;   // duplicates OK for min

        u64 acc[NW];
        #pragma unroll
        for (int i = 0; i < NW; i++) acc[i] = 0ull;

        const ulonglong2* kp = Ksh + sl;
        #pragma unroll
        for (int l = 0; l < PLS; l++) {
            ulonglong2 kv = kp[l * SPB];     // lanes distinct: 4 wavefronts
            #pragma unroll
            for (int i = 0; i < NW; i++) {
                ulonglong2 xv = Xsh[gw + l + i];   // warp-broadcast
                fma2(acc[i], xv.x, kv.x);
                fma2(acc[i], xv.y, kv.y);
            }
        }
        #pragma unroll
        for (int i = 0; i < NW; i++) {
            float lo, hi; upk2(lo, hi, acc[i]);
            rmin = fminf(rmin, lo + hi);
        }
    }
    atomicMin(&g_amin[b * PNS + sBase + sl], fenc(rmin));
}

// ---------------------------------------------------------------------------
// Finish: out[b,s] = (decoded min + k2[s]) / LS
__global__ void finish_kernel(const float* __restrict__ ker,
                              float* __restrict__ out) {
    int i = blockIdx.x * blockDim.x + threadIdx.x;
    if (i >= PB * PNS) return;
    int s = i % PNS;
    float k2 = 0.f;
    const float* kp = ker + s * PLS * PC;
    #pragma unroll 8
    for (int j = 0; j < PLS * PC; j++) {
        float v = kp[j];
        k2 += v * v;
    }
    out[i] = (fdec(g_amin[i]) + k2) * (1.0f / (float)PLS);
}

// ---------------------------------------------------------------------------
extern "C" void kernel_launch(void* const* d_in, const int* in_sizes, int n_in,
                              void* d_out, int out_size) {
    const float* data = (const float*)d_in[0];   // [32, 8192, 3]
    const float* ker  = (const float*)d_in[1];   // [256, 32, 3]
    float* out = (float*)d_out;                  // [32, 256]

    pack_x_kernel<<<(PB * PT + 255) / 256, 256>>>(data);
    pack_k_kernel<<<(PNS * PLS + 255) / 256, 256>>>(ker);
    init_amin_kernel<<<(PB * PNS + 255) / 256, 256>>>();

    dim3 grid(NCHUNK, NSB, PB);
    shapelet_main_kernel<<<grid, THREADS>>>();

    finish_kernel<<<(PB * PNS + 255) / 256, 256>>>(ker, out);
}

// round 3
// speedup vs baseline: 1.0115x; 1.0106x over previous
#include <cuda_runtime.h>

// Problem constants
#define PB   32
#define PT   8192
#define PC   3
#define PNS  256
#define PLS  32
#define PW   (PT - PLS + 1)   // 8161

// Tiling
#define NCHUNK  19
#define WCHUNK  432               // 19*432 = 8208 >= 8161
#define SPB     64                // shapelets per block
#define NSB     (PNS / SPB)       // 4
#define NGROUP  2
#define NW      8
#define THREADS (SPB * NGROUP)    // 128
#define STRIP   (WCHUNK + PLS - 1)  // 463

typedef unsigned long long u64;
typedef unsigned int u32;

// Device scratch (allocations forbidden)
__device__ ulonglong2 g_X[PB * PT];     // packed (x0,x1 | x2,|x|^2)
__device__ ulonglong2 g_Kp[PLS * PNS];  // [l][s]: (-2k0,-2k1 | -2k2, 1)
__device__ u32        g_amin[PB * PNS]; // encoded-uint running min

__device__ __forceinline__ void fma2(u64& d, u64 a, u64 b) {
    asm("fma.rn.f32x2 %0, %1, %2, %0;" : "+l"(d) : "l"(a), "l"(b));
}
__device__ __forceinline__ void upk2(float& lo, float& hi, u64 v) {
    asm("mov.b64 {%0, %1}, %2;" : "=f"(lo), "=f"(hi) : "l"(v));
}
// order-preserving float<->uint encoding for atomicMin on floats
__device__ __forceinline__ u32 fenc(float f) {
    u32 u = __float_as_uint(f);
    return (u & 0x80000000u) ? ~u : (u | 0x80000000u);
}
__device__ __forceinline__ float fdec(u32 u) {
    u32 b = (u & 0x80000000u) ? (u & 0x7FFFFFFFu) : ~u;
    return __uint_as_float(b);
}

// ---------------------------------------------------------------------------
// Fused prep: pack X, pack K', init amin
__global__ void prep_kernel(const float* __restrict__ data,
                            const float* __restrict__ ker) {
    int i = blockIdx.x * blockDim.x + threadIdx.x;
    if (i < PB * PT) {
        float x0 = data[i * 3 + 0];
        float x1 = data[i * 3 + 1];
        float x2 = data[i * 3 + 2];
        reinterpret_cast<float4*>(g_X)[i] =
            make_float4(x0, x1, x2, x0 * x0 + x1 * x1 + x2 * x2);
    }
    if (i < PNS * PLS) {
        int s = i / PLS, l = i % PLS;
        float k0 = ker[i * 3 + 0];
        float k1 = ker[i * 3 + 1];
        float k2 = ker[i * 3 + 2];
        reinterpret_cast<float4*>(g_Kp)[l * PNS + s] =
            make_float4(-2.f * k0, -2.f * k1, -2.f * k2, 1.0f);
    }
    if (i < PB * PNS) g_amin[i] = 0xFFFFFFFFu;
}

// ---------------------------------------------------------------------------
// Main: rmin[b,s] over chunk windows of sum_l dot4(X[w+l], Kp[s,l]); atomicMin.
__global__ __launch_bounds__(THREADS, 4) void shapelet_main_kernel() {
    __shared__ ulonglong2 Ksh[PLS * SPB];   // [l][sl]
    __shared__ ulonglong2 Xsh[STRIP];

    int chunk = blockIdx.x;
    int sblk  = blockIdx.y;
    int b     = blockIdx.z;
    int tid   = threadIdx.x;
    int sl    = tid % SPB;
    int g     = tid / SPB;                   // warp-uniform (SPB=64)
    int sBase = sblk * SPB;
    int w0    = chunk * WCHUNK;
    int wendL = PW - w0; if (wendL > WCHUNK) wendL = WCHUNK;

    for (int i = tid; i < PLS * SPB; i += THREADS) {
        int l = i / SPB, s = i % SPB;
        Ksh[i] = g_Kp[l * PNS + sBase + s];
    }
    const ulonglong2* Xg = g_X + b * PT;
    for (int i = tid; i < STRIP; i += THREADS) {
        int t = w0 + i; if (t > PT - 1) t = PT - 1;   // clamp; never wins min
        Xsh[i] = Xg[t];
    }
    __syncthreads();

    float rmin = 3.4e38f;
    for (int pb = 0; pb < wendL; pb += NGROUP * NW) {
        int gw = pb + g * NW;
        if (gw > wendL - NW) gw = wendL - NW;   // duplicates OK for min

        u64 acc[NW];
        #pragma unroll
        for (int i = 0; i < NW; i++) acc[i] = 0ull;

        // rotating register window: xr holds X[gw+l .. gw+l+7] entering lag l
        ulonglong2 xr[NW];
        #pragma unroll
        for (int i = 0; i < NW; i++) xr[i] = Xsh[gw + i];

        const ulonglong2* kp = Ksh + sl;
        #pragma unroll
        for (int l = 0; l < PLS; l++) {
            ulonglong2 kv = kp[l * SPB];
            #pragma unroll
            for (int i = 0; i < NW; i++) {
                ulonglong2 xv = xr[(l + i) % NW];
                fma2(acc[i], xv.x, kv.x);
                fma2(acc[i], xv.y, kv.y);
            }
            if (l < PLS - 1) xr[l % NW] = Xsh[gw + NW + l];  // shift in one value
        }
        #pragma unroll
        for (int i = 0; i < NW; i++) {
            float lo, hi; upk2(lo, hi, acc[i]);
            rmin = fminf(rmin, lo + hi);
        }
    }
    atomicMin(&g_amin[b * PNS + sBase + sl], fenc(rmin));
}

// ---------------------------------------------------------------------------
// Finish: out[b,s] = (decoded min + k2[s]) / LS
__global__ void finish_kernel(const float* __restrict__ ker,
                              float* __restrict__ out) {
    int i = blockIdx.x * blockDim.x + threadIdx.x;
    if (i >= PB * PNS) return;
    int s = i % PNS;
    float k2 = 0.f;
    const float* kp = ker + s * PLS * PC;
    #pragma unroll 8
    for (int j = 0; j < PLS * PC; j++) {
        float v = kp[j];
        k2 += v * v;
    }
    out[i] = (fdec(g_amin[i]) + k2) * (1.0f / (float)PLS);
}

// ---------------------------------------------------------------------------
extern "C" void kernel_launch(void* const* d_in, const int* in_sizes, int n_in,
                              void* d_out, int out_size) {
    const float* data = (const float*)d_in[0];   // [32, 8192, 3]
    const float* ker  = (const float*)d_in[1];   // [256, 32, 3]
    float* out = (float*)d_out;                  // [32, 256]

    prep_kernel<<<(PB * PT + 255) / 256, 256>>>(data, ker);

    dim3 grid(NCHUNK, NSB, PB);
    shapelet_main_kernel<<<grid, THREADS>>>();

    finish_kernel<<<(PB * PNS + 255) / 256, 256>>>(ker, out);
}

// round 4
// speedup vs baseline: 1.4011x; 1.3851x over previous
#include <cuda_runtime.h>

// Problem constants
#define PB   32
#define PT   8192
#define PC   3
#define PNS  256
#define PLS  32
#define PW   (PT - PLS + 1)   // 8161

// Tiling
#define NCHUNK  19
#define WCHUNK  432                 // 19*432 = 8208 >= 8161, divisible by 16
#define SPB     64                  // shapelets per block
#define NSB     (PNS / SPB)         // 4
#define NGROUP  2
#define THREADS (SPB * NGROUP)      // 128
#define STRIP   (WCHUNK + PLS - 1)  // 463

typedef unsigned long long u64;
typedef unsigned int u32;

// Device scratch (allocations forbidden)
__device__ ulonglong2 g_X12[PB * PT];   // (pack(x0[t],x0[t+1]) , pack(x1[t],x1[t+1]))
__device__ u64        g_X2[PB * PT];    // pack(x2[t], x2[t+1])
__device__ float      g_d2[PB * PT];    // per-timestep squared norm
__device__ float      g_a2[PB * PW];    // sliding-window squared norms
__device__ float      g_K0[PLS * PNS];  // [l][s] = -2*k0
__device__ float      g_K1[PLS * PNS];
__device__ float      g_K2[PLS * PNS];
__device__ u32        g_amin[PB * PNS]; // encoded-uint running min

__device__ __forceinline__ u64 pk2(float lo, float hi) {
    u64 r; asm("mov.b64 %0, {%1, %2};" : "=l"(r) : "f"(lo), "f"(hi)); return r;
}
__device__ __forceinline__ void upk2(float& lo, float& hi, u64 v) {
    asm("mov.b64 {%0, %1}, %2;" : "=f"(lo), "=f"(hi) : "l"(v));
}
__device__ __forceinline__ void fma2(u64& d, u64 a, u64 b) {
    asm("fma.rn.f32x2 %0, %1, %2, %0;" : "+l"(d) : "l"(a), "l"(b));
}
// order-preserving float<->uint encoding for atomicMin on floats
__device__ __forceinline__ u32 fenc(float f) {
    u32 u = __float_as_uint(f);
    return (u & 0x80000000u) ? ~u : (u | 0x80000000u);
}
__device__ __forceinline__ float fdec(u32 u) {
    u32 b = (u & 0x80000000u) ? (u & 0x7FFFFFFFu) : ~u;
    return __uint_as_float(b);
}

// ---------------------------------------------------------------------------
// Prep: pack X pairs (SoA), d2, K planes (-2k), init amin
__global__ void prep_kernel(const float* __restrict__ data,
                            const float* __restrict__ ker) {
    int i = blockIdx.x * blockDim.x + threadIdx.x;
    if (i < PB * PT) {
        int t = i % PT;
        const float* p = data + (size_t)i * 3;
        float x0 = p[0], x1 = p[1], x2 = p[2];
        float y0 = x0, y1 = x1, y2 = x2;
        if (t < PT - 1) { y0 = p[3]; y1 = p[4]; y2 = p[5]; }
        ulonglong2 v; v.x = pk2(x0, y0); v.y = pk2(x1, y1);
        g_X12[i] = v;
        g_X2[i]  = pk2(x2, y2);
        g_d2[i]  = x0 * x0 + x1 * x1 + x2 * x2;
    }
    if (i < PNS * PLS) {
        int s = i / PLS, l = i % PLS;
        g_K0[l * PNS + s] = -2.f * ker[i * 3 + 0];
        g_K1[l * PNS + s] = -2.f * ker[i * 3 + 1];
        g_K2[l * PNS + s] = -2.f * ker[i * 3 + 2];
    }
    if (i < PB * PNS) g_amin[i] = 0xFFFFFFFFu;
}

// Sliding-window norms: a2[b,w] = sum_{j<LS} d2[b, w+j]
__global__ void a2_kernel() {
    int i = blockIdx.x * blockDim.x + threadIdx.x;
    if (i >= PB * PW) return;
    int b = i / PW, w = i % PW;
    const float* d = g_d2 + b * PT + w;
    float s = 0.f;
    #pragma unroll
    for (int j = 0; j < PLS; j++) s += d[j];
    g_a2[i] = s;
}

// ---------------------------------------------------------------------------
// Main: acc(pair) = sum_l sum_c X2[c][w+l] * splat(-2k[s,l,c]); min(a2 + acc).
__global__ __launch_bounds__(THREADS, 4) void shapelet_main_kernel() {
    __shared__ float Ksh0[PLS * SPB];
    __shared__ float Ksh1[PLS * SPB];
    __shared__ float Ksh2[PLS * SPB];
    __shared__ ulonglong2 X12sh[STRIP];
    __shared__ u64        X2sh[STRIP];
    __shared__ float      a2sh[WCHUNK];

    int chunk = blockIdx.x;
    int sblk  = blockIdx.y;
    int b     = blockIdx.z;
    int tid   = threadIdx.x;
    int sl    = tid % SPB;
    int g     = tid / SPB;                 // warp-uniform (SPB=64)
    int sBase = sblk * SPB;
    int w0    = chunk * WCHUNK;

    // K planes: vectorized fill, 512 float4 per plane
    for (int i = tid; i < (PLS * SPB) / 4; i += THREADS) {
        int l = i >> 4, q = i & 15;
        const float4* s0 = (const float4*)(g_K0 + l * PNS + sBase);
        const float4* s1 = (const float4*)(g_K1 + l * PNS + sBase);
        const float4* s2 = (const float4*)(g_K2 + l * PNS + sBase);
        ((float4*)Ksh0)[i] = s0[q];
        ((float4*)Ksh1)[i] = s1[q];
        ((float4*)Ksh2)[i] = s2[q];
    }
    const ulonglong2* Xg12 = g_X12 + b * PT;
    const u64*        Xg2  = g_X2  + b * PT;
    for (int i = tid; i < STRIP; i += THREADS) {
        int t = w0 + i; if (t > PT - 1) t = PT - 1;
        X12sh[i] = Xg12[t];
        X2sh[i]  = Xg2[t];
    }
    const float* a2g = g_a2 + b * PW;
    for (int i = tid; i < WCHUNK; i += THREADS) {
        int w = w0 + i;
        a2sh[i] = (w < PW) ? a2g[w] : 1e30f;   // poison phantom windows
    }
    __syncthreads();

    float rmin = 3.4e38f;
    for (int pb = 0; pb < WCHUNK; pb += 16) {
        int gw = pb + g * 8;                 // even; 8 windows = 4 pairs

        u64 acc[4] = {0ull, 0ull, 0ull, 0ull};
        ulonglong2 xr01[8];
        u64        xr2[8];
        #pragma unroll
        for (int i = 0; i < 8; i++) { xr01[i] = X12sh[gw + i]; xr2[i] = X2sh[gw + i]; }

        #pragma unroll
        for (int l = 0; l < PLS; l++) {
            float k0 = Ksh0[l * SPB + sl];
            float k1 = Ksh1[l * SPB + sl];
            float k2 = Ksh2[l * SPB + sl];
            u64 kv0 = pk2(k0, k0), kv1 = pk2(k1, k1), kv2 = pk2(k2, k2);
            #pragma unroll
            for (int p = 0; p < 4; p++) {
                int j = (l + 2 * p) & 7;
                fma2(acc[p], xr01[j].x, kv0);
                fma2(acc[p], xr01[j].y, kv1);
                fma2(acc[p], xr2[j],    kv2);
            }
            if (l < PLS - 1) {               // shift in one timestep
                xr01[l & 7] = X12sh[gw + 8 + l];
                xr2[l & 7]  = X2sh[gw + 8 + l];
            }
        }
        #pragma unroll
        for (int p = 0; p < 4; p++) {
            float lo, hi; upk2(lo, hi, acc[p]);
            float2 aa = *(const float2*)(a2sh + gw + 2 * p);   // gw even -> aligned
            rmin = fminf(rmin, fminf(lo + aa.x, hi + aa.y));
        }
    }
    atomicMin(&g_amin[b * PNS + sBase + sl], fenc(rmin));
}

// ---------------------------------------------------------------------------
// Finish: out[b,s] = (decoded min + k2[s]) / LS
__global__ void finish_kernel(const float* __restrict__ ker,
                              float* __restrict__ out) {
    int i = blockIdx.x * blockDim.x + threadIdx.x;
    if (i >= PB * PNS) return;
    int s = i % PNS;
    float k2 = 0.f;
    const float* kp = ker + s * PLS * PC;
    #pragma unroll 8
    for (int j = 0; j < PLS * PC; j++) {
        float v = kp[j];
        k2 += v * v;
    }
    out[i] = (fdec(g_amin[i]) + k2) * (1.0f / (float)PLS);
}

// ---------------------------------------------------------------------------
extern "C" void kernel_launch(void* const* d_in, const int* in_sizes, int n_in,
                              void* d_out, int out_size) {
    const float* data = (const float*)d_in[0];   // [32, 8192, 3]
    const float* ker  = (const float*)d_in[1];   // [256, 32, 3]
    float* out = (float*)d_out;                  // [32, 256]

    prep_kernel<<<(PB * PT + 255) / 256, 256>>>(data, ker);
    a2_kernel<<<(PB * PW + 255) / 256, 256>>>();

    dim3 grid(NCHUNK, NSB, PB);
    shapelet_main_kernel<<<grid, THREADS>>>();

    finish_kernel<<<(PB * PNS + 255) / 256, 256>>>(ker, out);
}

// round 6
// speedup vs baseline: 1.7033x; 1.2157x over previous
#include <cuda_runtime.h>
#include <cuda_bf16.h>

// Problem constants
#define PB   32
#define PT   8192
#define PC   3
#define PNS  256
#define PLS  32
#define PW   (PT - PLS + 1)        // 8161

#define KF      96                 // K = LS*C
#define KPAD    128                // global K row pad (u16 elements)
#define NTILE   64                 // windows per item
#define WTILES  (PT / NTILE)       // 128
#define NPAIRIT (PB * WTILES)      // 4096 (b, wtile) items
#define THREADS 256

#define FLATN   (PT * PC)          // 24576
#define PTF     (FLATN + 96)       // phase-array padded length (24672)

#define ASTR_B  208                // 104 bf16 per row (conflict-free ldmatrix)
#define SM_AH   0                  // 128*208 = 26624
#define SM_AL   26624
#define SM_BH   53248              // 64*208 = 13312
#define SM_BL   66560
#define SM_A2   79872              // 64 floats
#define SM_TOT  80384

typedef unsigned int u32;
typedef unsigned short u16;
typedef unsigned long long u64;

// Device scratch (allocations forbidden)
__device__ __align__(16) u16 g_fhi[PB * FLATN];     // flat bf16 hi
__device__ __align__(16) u16 g_flo[PB * FLATN];     // flat bf16 lo
__device__ __align__(16) u16 g_xhi[8 * PB * PTF];   // 8 phase-shifted copies
__device__ __align__(16) u16 g_xlo[8 * PB * PTF];
__device__ __align__(16) u16 g_khi[PNS * KPAD];     // bf16(-2k) hi
__device__ __align__(16) u16 g_klo[PNS * KPAD];     // bf16(-2k) lo
__device__ float g_d2[PB * PT];
__device__ float g_a2[PB * PW];
__device__ float g_k2[PNS];
__device__ u32   g_amin[PB * PNS];

// ---------------------------------------------------------------------------
__device__ __forceinline__ u32 smem_u32(const void* p) {
    u32 a; asm("{ .reg .u64 t; cvta.to.shared.u64 t, %1; cvt.u32.u64 %0, t; }"
               : "=r"(a) : "l"(p));
    return a;
}
__device__ __forceinline__ u32 fenc(float f) {
    u32 u = __float_as_uint(f);
    return (u & 0x80000000u) ? ~u : (u | 0x80000000u);
}
__device__ __forceinline__ float fdec(u32 u) {
    u32 b = (u & 0x80000000u) ? (u & 0x7FFFFFFFu) : ~u;
    return __uint_as_float(b);
}

#define LDSM4(r0, r1, r2, r3, addr) \
    asm volatile("ldmatrix.sync.aligned.m8n8.x4.shared.b16 {%0,%1,%2,%3}, [%4];" \
        : "=r"(r0), "=r"(r1), "=r"(r2), "=r"(r3) : "r"(addr))

#define MMA16816(d, a0, a1, a2, a3, b0, b1) \
    asm volatile("mma.sync.aligned.m16n8k16.row.col.f32.bf16.bf16.f32 " \
        "{%0,%1,%2,%3}, {%4,%5,%6,%7}, {%8,%9}, {%0,%1,%2,%3};" \
        : "+f"((d)[0]), "+f"((d)[1]), "+f"((d)[2]), "+f"((d)[3]) \
        : "r"(a0), "r"(a1), "r"(a2), "r"(a3), "r"(b0), "r"(b1))

// ---------------------------------------------------------------------------
// prep1: flat bf16 hi/lo split, d2, K(-2k) hi/lo, amin init, k2
__global__ void prep1_kernel(const float* __restrict__ data,
                             const float* __restrict__ ker) {
    int i = blockIdx.x * blockDim.x + threadIdx.x;
    if (i < PB * PT) {
        const float* p = data + (size_t)i * 3;
        float x0 = p[0], x1 = p[1], x2 = p[2];
        g_d2[i] = x0 * x0 + x1 * x1 + x2 * x2;
        float xs[3] = {x0, x1, x2};
        int e = i * 3;
        #pragma unroll
        for (int c = 0; c < 3; c++) {
            __nv_bfloat16 hi = __float2bfloat16(xs[c]);
            __nv_bfloat16 lo = __float2bfloat16(xs[c] - __bfloat162float(hi));
            g_fhi[e + c] = __bfloat16_as_ushort(hi);
            g_flo[e + c] = __bfloat16_as_ushort(lo);
        }
    }
    if (i < PNS * PLS) {
        int s = i / PLS, l = i % PLS;
        #pragma unroll
        for (int c = 0; c < 3; c++) {
            float v = -2.f * ker[i * 3 + c];
            __nv_bfloat16 hi = __float2bfloat16(v);
            __nv_bfloat16 lo = __float2bfloat16(v - __bfloat162float(hi));
            g_khi[s * KPAD + l * 3 + c] = __bfloat16_as_ushort(hi);
            g_klo[s * KPAD + l * 3 + c] = __bfloat16_as_ushort(lo);
        }
    }
    if (i < PB * PNS) g_amin[i] = 0xFFFFFFFFu;
    if (i < PNS) {
        float k2 = 0.f;
        const float* kp = ker + i * KF;
        #pragma unroll 8
        for (int j = 0; j < KF; j++) { float v = kp[j]; k2 += v * v; }
        g_k2[i] = k2;
    }
}

// prep2: 8 phase-shifted copies (array_p[i] = flat[i+p]), coalesced u32 writes
__global__ void prep2_kernel() {
    const int HP = PTF / 2;
    int j = blockIdx.x * blockDim.x + threadIdx.x;
    if (j >= 8 * PB * HP) return;
    int i2 = j % HP;
    int r  = j / HP;            // = p*PB + b
    int b  = r % PB;
    int p  = r / PB;
    int e0 = 2 * i2 + p;
    const u16* fh = g_fhi + b * FLATN;
    const u16* fl = g_flo + b * FLATN;
    u16 h0 = 0, h1 = 0, l0 = 0, l1 = 0;
    if (e0 < FLATN)     { h0 = fh[e0];     l0 = fl[e0]; }
    if (e0 + 1 < FLATN) { h1 = fh[e0 + 1]; l1 = fl[e0 + 1]; }
    ((u32*)g_xhi)[r * HP + i2] = (u32)h0 | ((u32)h1 << 16);
    ((u32*)g_xlo)[r * HP + i2] = (u32)l0 | ((u32)l1 << 16);
}

// sliding-window norms
__global__ void a2_kernel() {
    int i = blockIdx.x * blockDim.x + threadIdx.x;
    if (i >= PB * PW) return;
    int b = i / PW, w = i % PW;
    const float* d = g_d2 + b * PT + w;
    float s = 0.f;
    #pragma unroll
    for (int j = 0; j < PLS; j++) s += d[j];
    g_a2[i] = s;
}

// ---------------------------------------------------------------------------
// Main: mma.sync bf16 3-term GEMM with fused min epilogue. Persistent CTAs.
__global__ __launch_bounds__(THREADS, 2) void mma_main_kernel() {
    extern __shared__ __align__(16) char smem[];
    u32 sbase = smem_u32(smem);
    int tid  = threadIdx.x;
    int lane = tid & 31;
    int warp = tid >> 5;                     // 0..7 -> M rows warp*16
    int Mtile  = blockIdx.x & 1;             // shapelet half
    int pairId = blockIdx.x >> 1;
    int npairs = gridDim.x >> 1;

    // ---- Build A tiles (hi/lo), resident whole kernel. Rows stride 104 elem.
    for (int j = tid; j < 512; j += THREADS) {
        int term = j >> 8, r = j & 255, row = r >> 1, half = r & 1;
        const uint4* src = (const uint4*)(term ? g_klo : g_khi)
                           + (size_t)(Mtile * 128 + row) * (KPAD / 8);
        char* dst = smem + (term ? SM_AL : SM_AH) + row * ASTR_B + half * 96;
        #pragma unroll
        for (int q = 0; q < 6; q++) ((uint4*)dst)[q] = src[half * 6 + q];
    }

    // ---- Per-thread ldmatrix offsets
    int ti = lane >> 3, l8 = lane & 7;
    u32 aoff = (u32)((((ti & 1) * 8 + l8) * ASTR_B) + (ti >> 1) * 16)
             + (u32)(warp * 16 * ASTR_B);
    u32 boff = (u32)((((ti >> 1) * 8 + l8) * ASTR_B) + (ti & 1) * 16);

    // ---- B prefetch roles
    int bterm = tid >> 7, rr = tid & 127, brow = rr >> 1, bhalf = rr & 1;
    const u16* xsrc_base = bterm ? g_xlo : g_xhi;

    uint4 pv[6];
    float av = 0.f;

    // initial prefetch for item pairId
    {
        int b = pairId >> 7, wt = pairId & 127;
        int E = 3 * (wt * NTILE + brow), p = E & 7;
        const uint4* src = (const uint4*)(xsrc_base + (size_t)(p * PB + b) * PTF + (E - p));
        #pragma unroll
        for (int q = 0; q < 6; q++) pv[q] = src[bhalf * 6 + q];
        if (tid >= 192) {
            int w = wt * NTILE + (tid - 192);
            av = (w < PW) ? g_a2[b * PW + w] : 1e30f;
        }
    }

    for (int u = pairId; u < NPAIRIT; u += npairs) {
        int b = u >> 7;
        __syncthreads();   // prior item's reads done (first iter: A build done)
        {   // store prefetched B tile + a2
            char* dst = smem + (bterm ? SM_BL : SM_BH) + brow * ASTR_B + bhalf * 96;
            #pragma unroll
            for (int q = 0; q < 6; q++) ((uint4*)dst)[q] = pv[q];
            if (tid >= 192) ((float*)(smem + SM_A2))[tid - 192] = av;
        }
        __syncthreads();

        // prefetch next item (hidden under mma)
        int un = u + npairs;
        if (un < NPAIRIT) {
            int bn = un >> 7, wtn = un & 127;
            int E = 3 * (wtn * NTILE + brow), p = E & 7;
            const uint4* src = (const uint4*)(xsrc_base + (size_t)(p * PB + bn) * PTF + (E - p));
            #pragma unroll
            for (int q = 0; q < 6; q++) pv[q] = src[bhalf * 6 + q];
            if (tid >= 192) {
                int w = wtn * NTILE + (tid - 192);
                av = (w < PW) ? g_a2[bn * PW + w] : 1e30f;
            }
        }

        // ---- 3-term GEMM: D = Ah*Bh + Ah*Bl + Al*Bh  (K=96, 6 ksteps/term)
        float d[8][4];
        #pragma unroll
        for (int jb = 0; jb < 8; jb++)
            #pragma unroll
            for (int q = 0; q < 4; q++) d[jb][q] = 0.f;

        const u32 aB[3] = {SM_AH, SM_AH, SM_AL};
        const u32 bB[3] = {SM_BH, SM_BL, SM_BH};
        #pragma unroll
        for (int t3 = 0; t3 < 3; t3++) {
            u32 ab = sbase + aB[t3] + aoff;
            u32 bb = sbase + bB[t3] + boff;
            #pragma unroll
            for (int ks = 0; ks < 6; ks++) {
                u32 a0, a1, a2r, a3;
                LDSM4(a0, a1, a2r, a3, ab + ks * 32);
                #pragma unroll
                for (int jp = 0; jp < 4; jp++) {
                    u32 b0, b1, b2, b3;
                    LDSM4(b0, b1, b2, b3, bb + jp * (16 * ASTR_B) + ks * 32);
                    MMA16816(d[2 * jp],     a0, a1, a2r, a3, b0, b1);
                    MMA16816(d[2 * jp + 1], a0, a1, a2r, a3, b2, b3);
                }
            }
        }

        // ---- Epilogue: add a2, min over the 64 windows, atomicMin per shapelet
        int g = lane >> 2, tg = lane & 3;
        const float* a2sh = (const float*)(smem + SM_A2);
        float m0v = 3.4e38f, m1v = 3.4e38f;
        #pragma unroll
        for (int jb = 0; jb < 8; jb++) {
            float aa0 = a2sh[jb * 8 + tg * 2];
            float aa1 = a2sh[jb * 8 + tg * 2 + 1];
            m0v = fminf(m0v, fminf(d[jb][0] + aa0, d[jb][1] + aa1));
            m1v = fminf(m1v, fminf(d[jb][2] + aa0, d[jb][3] + aa1));
        }
        m0v = fminf(m0v, __shfl_xor_sync(0xFFFFFFFFu, m0v, 1));
        m0v = fminf(m0v, __shfl_xor_sync(0xFFFFFFFFu, m0v, 2));
        m1v = fminf(m1v, __shfl_xor_sync(0xFFFFFFFFu, m1v, 1));
        m1v = fminf(m1v, __shfl_xor_sync(0xFFFFFFFFu, m1v, 2));
        if (tg == 0) {
            int srow = Mtile * 128 + warp * 16 + g;
            atomicMin(&g_amin[b * PNS + srow],     fenc(m0v));
            atomicMin(&g_amin[b * PNS + srow + 8], fenc(m1v));
        }
    }
}

// ---------------------------------------------------------------------------
__global__ void finish_kernel(float* __restrict__ out) {
    int i = blockIdx.x * blockDim.x + threadIdx.x;
    if (i >= PB * PNS) return;
    out[i] = (fdec(g_amin[i]) + g_k2[i % PNS]) * (1.0f / (float)PLS);
}

// ---------------------------------------------------------------------------
extern "C" void kernel_launch(void* const* d_in, const int* in_sizes, int n_in,
                              void* d_out, int out_size) {
    const float* data = (const float*)d_in[0];   // [32, 8192, 3]
    const float* ker  = (const float*)d_in[1];   // [256, 32, 3]
    float* out = (float*)d_out;                  // [32, 256]

    cudaFuncSetAttribute(mma_main_kernel,
                         cudaFuncAttributeMaxDynamicSharedMemorySize, SM_TOT);
    int dev = 0, nsm = 148;
    cudaGetDevice(&dev);
    cudaDeviceGetAttribute(&nsm, cudaDevAttrMultiProcessorCount, dev);

    prep1_kernel<<<(PB * PT + 255) / 256, 256>>>(data, ker);
    prep2_kernel<<<(8 * PB * (PTF / 2) + 255) / 256, 256>>>();
    a2_kernel<<<(PB * PW + 255) / 256, 256>>>();

    mma_main_kernel<<<2 * nsm, THREADS, SM_TOT>>>();

    finish_kernel<<<(PB * PNS + 255) / 256, 256>>>(out);
}

// round 8
// speedup vs baseline: 2.7036x; 1.5873x over previous
#include <cuda_runtime.h>
#include <cuda_bf16.h>

// Problem constants
#define PB   32
#define PT   8192
#define PC   3
#define PLS  32
#define PNS  256
#define PW   (PT - PLS + 1)        // 8161

#define KF      96                 // K = LS*C
#define KPAD    128                // global K row pad (u16 elements)
#define NTILE   64                 // windows per item
#define WTILES  (PT / NTILE)       // 128
#define NITEMS  (PB * WTILES)      // 4096
#define THREADS 256

#define FLATN   (PT * PC)          // 24576
#define PTF     (FLATN + 96)       // phase-array padded length (24672)

#define BSTR    208                // B row stride bytes (104 bf16, conflict-free)
#define BTERM   13312              // 64 rows * 208
#define BUFSZ   26624              // hi + lo
#define SM_A2   53248              // 2 x 64 floats
#define SM_TOT  53760

typedef unsigned int u32;
typedef unsigned short u16;
typedef unsigned long long u64;

// Device scratch (allocations forbidden)
__device__ __align__(16) u16 g_fhi[PB * FLATN];     // flat bf16 hi
__device__ __align__(16) u16 g_flo[PB * FLATN];     // flat bf16 lo
__device__ __align__(16) u16 g_xhi[8 * PB * PTF];   // 8 phase-shifted copies
__device__ __align__(16) u16 g_xlo[8 * PB * PTF];
__device__ __align__(16) u16 g_khi[PNS * KPAD];     // bf16(-2k) hi
__device__ __align__(16) u16 g_klo[PNS * KPAD];     // bf16(-2k) lo
__device__ float g_d2[PB * PT];
__device__ float g_a2[PB * PT];                     // padded; >=PW poisoned
__device__ float g_k2[PNS];
__device__ u32   g_amin[PB * PNS];

// ---------------------------------------------------------------------------
__device__ __forceinline__ u32 smem_u32(const void* p) {
    u32 a; asm("{ .reg .u64 t; cvta.to.shared.u64 t, %1; cvt.u32.u64 %0, t; }"
               : "=r"(a) : "l"(p));
    return a;
}
__device__ __forceinline__ u32 fenc(float f) {
    u32 u = __float_as_uint(f);
    return (u & 0x80000000u) ? ~u : (u | 0x80000000u);
}
__device__ __forceinline__ float fdec(u32 u) {
    u32 b = (u & 0x80000000u) ? (u & 0x7FFFFFFFu) : ~u;
    return __uint_as_float(b);
}

#define LDSM4(r0, r1, r2, r3, addr) \
    asm volatile("ldmatrix.sync.aligned.m8n8.x4.shared.b16 {%0,%1,%2,%3}, [%4];" \
        : "=r"(r0), "=r"(r1), "=r"(r2), "=r"(r3) : "r"(addr))

#define MMA16816(d, a0, a1, a2, a3, b0, b1) \
    asm volatile("mma.sync.aligned.m16n8k16.row.col.f32.bf16.bf16.f32 " \
        "{%0,%1,%2,%3}, {%4,%5,%6,%7}, {%8,%9}, {%0,%1,%2,%3};" \
        : "+f"((d)[0]), "+f"((d)[1]), "+f"((d)[2]), "+f"((d)[3]) \
        : "r"(a0), "r"(a1), "r"(a2), "r"(a3), "r"(b0), "r"(b1))

#define CPASYNC16(dst, src) \
    asm volatile("cp.async.cg.shared.global [%0], [%1], 16;" :: "r"(dst), "l"(src))
#define CPASYNC4(dst, src) \
    asm volatile("cp.async.ca.shared.global [%0], [%1], 4;" :: "r"(dst), "l"(src))

// ---------------------------------------------------------------------------
// prep1: flat bf16 hi/lo split, d2, K(-2k) hi/lo, amin init, k2
__global__ void prep1_kernel(const float* __restrict__ data,
                             const float* __restrict__ ker) {
    int i = blockIdx.x * blockDim.x + threadIdx.x;
    if (i < PB * PT) {
        const float* p = data + (size_t)i * 3;
        float x0 = p[0], x1 = p[1], x2 = p[2];
        g_d2[i] = x0 * x0 + x1 * x1 + x2 * x2;
        float xs[3] = {x0, x1, x2};
        int e = i * 3;
        #pragma unroll
        for (int c = 0; c < 3; c++) {
            __nv_bfloat16 hi = __float2bfloat16(xs[c]);
            __nv_bfloat16 lo = __float2bfloat16(xs[c] - __bfloat162float(hi));
            g_fhi[e + c] = __bfloat16_as_ushort(hi);
            g_flo[e + c] = __bfloat16_as_ushort(lo);
        }
    }
    if (i < PNS * PLS) {
        int s = i / PLS, l = i % PLS;
        #pragma unroll
        for (int c = 0; c < 3; c++) {
            float v = -2.f * ker[i * 3 + c];
            __nv_bfloat16 hi = __float2bfloat16(v);
            __nv_bfloat16 lo = __float2bfloat16(v - __bfloat162float(hi));
            g_khi[s * KPAD + l * 3 + c] = __bfloat16_as_ushort(hi);
            g_klo[s * KPAD + l * 3 + c] = __bfloat16_as_ushort(lo);
        }
    }
    if (i < PB * PNS) g_amin[i] = 0xFFFFFFFFu;
    if (i < PNS) {
        float k2 = 0.f;
        const float* kp = ker + i * KF;
        #pragma unroll 8
        for (int j = 0; j < KF; j++) { float v = kp[j]; k2 += v * v; }
        g_k2[i] = k2;
    }
}

// prep2: 8 phase-shifted copies (array_p[i] = flat[i+p]), coalesced u32 writes
__global__ void prep2_kernel() {
    const int HP = PTF / 2;
    int j = blockIdx.x * blockDim.x + threadIdx.x;
    if (j >= 8 * PB * HP) return;
    int i2 = j % HP;
    int r  = j / HP;            // = p*PB + b
    int b  = r % PB;
    int p  = r / PB;
    int e0 = 2 * i2 + p;
    const u16* fh = g_fhi + b * FLATN;
    const u16* fl = g_flo + b * FLATN;
    u16 h0 = 0, h1 = 0, l0 = 0, l1 = 0;
    if (e0 < FLATN)     { h0 = fh[e0];     l0 = fl[e0]; }
    if (e0 + 1 < FLATN) { h1 = fh[e0 + 1]; l1 = fl[e0 + 1]; }
    ((u32*)g_xhi)[r * HP + i2] = (u32)h0 | ((u32)h1 << 16);
    ((u32*)g_xlo)[r * HP + i2] = (u32)l0 | ((u32)l1 << 16);
}

// sliding-window norms, poison-padded to PT
__global__ void a2_kernel() {
    int i = blockIdx.x * blockDim.x + threadIdx.x;
    if (i >= PB * PT) return;
    int b = i / PT, w = i % PT;
    float s = 1e30f;
    if (w < PW) {
        const float* d = g_d2 + b * PT + w;
        s = 0.f;
        #pragma unroll
        for (int j = 0; j < PLS; j++) s += d[j];
    }
    g_a2[i] = s;
}

// ---------------------------------------------------------------------------
// issue cp.async group for one item into buffer `buf`
// 1536 16B copies: 2 terms x 64 rows x 12 quads (192B per row)
__device__ __forceinline__ void issue_item(u32 sbase, int buf, int b, int w0) {
    int tid = threadIdx.x;
    u32 bufbase = sbase + (u32)buf * BUFSZ;
    #pragma unroll
    for (int rep = 0; rep < 6; rep++) {
        int c = tid + rep * 256;            // 0..1535
        int term = c >> 9 >= 1 ? (c >= 768) : 0;   // c/768
        term = c / 768;
        int cc = c - term * 768;
        int row = cc / 12, q = cc - row * 12;
        int E = 3 * (w0 + row), p = E & 7;
        const u16* src = (term ? g_xlo : g_xhi)
                         + (size_t)(p * PB + b) * PTF + (E - p) + q * 8;
        u32 dst = bufbase + (u32)term * BTERM + (u32)row * BSTR + (u32)q * 16;
        CPASYNC16(dst, src);
    }
    if (tid < NTILE) {
        const float* src = g_a2 + (size_t)b * PT + w0 + tid;
        u32 dst = sbase + SM_A2 + (u32)buf * 256 + (u32)tid * 4;
        CPASYNC4(dst, src);
    }
    asm volatile("cp.async.commit_group;" ::: "memory");
}

// ---------------------------------------------------------------------------
// Main: persistent A fragments in registers, cp.async double-buffered B.
__global__ __launch_bounds__(THREADS, 1) void mma_main_kernel() {
    extern __shared__ __align__(16) char smem[];
    u32 sbase = smem_u32(smem);
    int tid  = threadIdx.x;
    int lane = tid & 31;
    int warp = tid >> 5;                 // 0..7 -> M rows warp*32..+31
    int g    = lane >> 2;                // 0..7
    int tg   = lane & 3;                 // 0..3

    // ---- Persistent A fragments (mma layout), loaded once via LDG
    u32 Ah[48], Al[48];                  // [ks*8 + mt*4 + q]
    {
        int r0 = warp * 32 + g;
        #pragma unroll
        for (int ks = 0; ks < 6; ks++) {
            #pragma unroll
            for (int mt = 0; mt < 2; mt++) {
                int r = r0 + mt * 16;
                int col = ks * 16 + tg * 2;
                const u16* ph = g_khi + (size_t)r * KPAD + col;
                const u16* pl = g_klo + (size_t)r * KPAD + col;
                int o = ks * 8 + mt * 4;
                Ah[o + 0] = *(const u32*)(ph);
                Ah[o + 1] = *(const u32*)(ph + 8 * KPAD);
                Ah[o + 2] = *(const u32*)(ph + 8);
                Ah[o + 3] = *(const u32*)(ph + 8 * KPAD + 8);
                Al[o + 0] = *(const u32*)(pl);
                Al[o + 1] = *(const u32*)(pl + 8 * KPAD);
                Al[o + 2] = *(const u32*)(pl + 8);
                Al[o + 3] = *(const u32*)(pl + 8 * KPAD + 8);
            }
        }
    }

    // ldmatrix B per-thread offset (proven mapping from R6)
    int ti = lane >> 3, l8 = lane & 7;
    u32 boff = (u32)((((ti >> 1) * 8 + l8) * BSTR) + (ti & 1) * 16);

    // ---- prologue: prefetch first item into buf 0
    int item0 = blockIdx.x;
    issue_item(sbase, 0, item0 >> 7, (item0 & 127) * NTILE);

    int buf = 0;
    for (int u = item0; u < NITEMS; u += gridDim.x) {
        int b = u >> 7;
        int un = u + gridDim.x;
        if (un < NITEMS) {
            issue_item(sbase, buf ^ 1, un >> 7, (un & 127) * NTILE);
            asm volatile("cp.async.wait_group 1;" ::: "memory");
        } else {
            asm volatile("cp.async.wait_group 0;" ::: "memory");
        }
        __syncthreads();

        // ---- 3-term GEMM on buf: D = Ah*Bh + Ah*Bl + Al*Bh
        float d[2][8][4];
        #pragma unroll
        for (int mt = 0; mt < 2; mt++)
            #pragma unroll
            for (int jb = 0; jb < 8; jb++)
                #pragma unroll
                for (int q = 0; q < 4; q++) d[mt][jb][q] = 0.f;

        u32 bhbase = sbase + (u32)buf * BUFSZ + boff;
        u32 blbase = bhbase + BTERM;
        #pragma unroll
        for (int ks = 0; ks < 6; ks++) {
            u32 bh[16], bl[16];
            #pragma unroll
            for (int jp = 0; jp < 4; jp++) {
                LDSM4(bh[jp*4+0], bh[jp*4+1], bh[jp*4+2], bh[jp*4+3],
                      bhbase + jp * (16 * BSTR) + ks * 32);
                LDSM4(bl[jp*4+0], bl[jp*4+1], bl[jp*4+2], bl[jp*4+3],
                      blbase + jp * (16 * BSTR) + ks * 32);
            }
            #pragma unroll
            for (int mt = 0; mt < 2; mt++) {
                int o = ks * 8 + mt * 4;
                #pragma unroll
                for (int jp = 0; jp < 4; jp++) {
                    MMA16816(d[mt][2*jp],   Ah[o], Ah[o+1], Ah[o+2], Ah[o+3],
                             bh[jp*4+0], bh[jp*4+1]);
                    MMA16816(d[mt][2*jp+1], Ah[o], Ah[o+1], Ah[o+2], Ah[o+3],
                             bh[jp*4+2], bh[jp*4+3]);
                    MMA16816(d[mt][2*jp],   Ah[o], Ah[o+1], Ah[o+2], Ah[o+3],
                             bl[jp*4+0], bl[jp*4+1]);
                    MMA16816(d[mt][2*jp+1], Ah[o], Ah[o+1], Ah[o+2], Ah[o+3],
                             bl[jp*4+2], bl[jp*4+3]);
                    MMA16816(d[mt][2*jp],   Al[o], Al[o+1], Al[o+2], Al[o+3],
                             bh[jp*4+0], bh[jp*4+1]);
                    MMA16816(d[mt][2*jp+1], Al[o], Al[o+1], Al[o+2], Al[o+3],
                             bh[jp*4+2], bh[jp*4+3]);
                }
            }
        }

        // ---- Epilogue: +a2, min over 64 windows, atomicMin per shapelet
        const float* a2sh = (const float*)(smem + SM_A2 + buf * 256);
        #pragma unroll
        for (int mt = 0; mt < 2; mt++) {
            float m0 = 3.4e38f, m1 = 3.4e38f;
            #pragma unroll
            for (int jb = 0; jb < 8; jb++) {
                float aa0 = a2sh[jb * 8 + tg * 2];
                float aa1 = a2sh[jb * 8 + tg * 2 + 1];
                m0 = fminf(m0, fminf(d[mt][jb][0] + aa0, d[mt][jb][1] + aa1));
                m1 = fminf(m1, fminf(d[mt][jb][2] + aa0, d[mt][jb][3] + aa1));
            }
            m0 = fminf(m0, __shfl_xor_sync(0xFFFFFFFFu, m0, 1));
            m0 = fminf(m0, __shfl_xor_sync(0xFFFFFFFFu, m0, 2));
            m1 = fminf(m1, __shfl_xor_sync(0xFFFFFFFFu, m1, 1));
            m1 = fminf(m1, __shfl_xor_sync(0xFFFFFFFFu, m1, 2));
            if (tg == 0) {
                int srow = warp * 32 + mt * 16 + g;
                atomicMin(&g_amin[b * PNS + srow],     fenc(m0));
                atomicMin(&g_amin[b * PNS + srow + 8], fenc(m1));
            }
        }
        __syncthreads();    // all reads of buf done before it is refilled
        buf ^= 1;
    }
}

// ---------------------------------------------------------------------------
__global__ void finish_kernel(float* __restrict__ out) {
    int i = blockIdx.x * blockDim.x + threadIdx.x;
    if (i >= PB * PNS) return;
    out[i] = (fdec(g_amin[i]) + g_k2[i % PNS]) * (1.0f / (float)PLS);
}

// ---------------------------------------------------------------------------
extern "C" void kernel_launch(void* const* d_in, const int* in_sizes, int n_in,
                              void* d_out, int out_size) {
    const float* data = (const float*)d_in[0];   // [32, 8192, 3]
    const float* ker  = (const float*)d_in[1];   // [256, 32, 3]
    float* out = (float*)d_out;                  // [32, 256]

    cudaFuncSetAttribute(mma_main_kernel,
                         cudaFuncAttributeMaxDynamicSharedMemorySize, SM_TOT);
    int dev = 0, nsm = 148;
    cudaGetDevice(&dev);
    cudaDeviceGetAttribute(&nsm, cudaDevAttrMultiProcessorCount, dev);
    if (nsm > NITEMS) nsm = NITEMS;

    prep1_kernel<<<(PB * PT + 255) / 256, 256>>>(data, ker);
    prep2_kernel<<<(8 * PB * (PTF / 2) + 255) / 256, 256>>>();
    a2_kernel<<<(PB * PT + 255) / 256, 256>>>();

    mma_main_kernel<<<nsm, THREADS, SM_TOT>>>();

    finish_kernel<<<(PB * PNS + 255) / 256, 256>>>(out);
}